// round 13
// baseline (speedup 1.0000x reference)
#include <cuda_runtime.h>
#include <cuda_fp16.h>

#define N_CELLS 100000
#define N_ISO   16
#define KP1     31
#define THREADS 256
#define BLOCKS_PER_SM 6
#define MAXGRID 2048

/* fp16 packed rows, 64B each (4 x float4): [u, s0..s15, 0*15] and [vhat_0..16, 0*15]. */
__device__ float4            g_hx[(size_t)N_CELLS * 4];
__device__ float4            g_hv[(size_t)N_CELLS * 4];
__device__ float             g_partials[MAXGRID];
__device__ unsigned int      g_ticket = 0;
__device__ unsigned int      g_bar_count = 0;
__device__ volatile unsigned g_phase = 0;

__device__ __forceinline__ float4 pack8h(const float* f)
{
    __half2 h0 = __floats2half2_rn(f[0], f[1]);
    __half2 h1 = __floats2half2_rn(f[2], f[3]);
    __half2 h2 = __floats2half2_rn(f[4], f[5]);
    __half2 h3 = __floats2half2_rn(f[6], f[7]);
    float4 o;
    o.x = __uint_as_float(*reinterpret_cast<unsigned*>(&h0));
    o.y = __uint_as_float(*reinterpret_cast<unsigned*>(&h1));
    o.z = __uint_as_float(*reinterpret_cast<unsigned*>(&h2));
    o.w = __uint_as_float(*reinterpret_cast<unsigned*>(&h3));
    return o;
}

__device__ __forceinline__ void as_h2(const float4 w, __half2* h)
{
    unsigned a0 = __float_as_uint(w.x), a1 = __float_as_uint(w.y);
    unsigned a2 = __float_as_uint(w.z), a3 = __float_as_uint(w.w);
    h[0] = *reinterpret_cast<__half2*>(&a0);
    h[1] = *reinterpret_cast<__half2*>(&a1);
    h[2] = *reinterpret_cast<__half2*>(&a2);
    h[3] = *reinterpret_cast<__half2*>(&a3);
}

__global__ __launch_bounds__(THREADS, BLOCKS_PER_SM) void fused_kernel(
    const float* __restrict__ u,
    const float* __restrict__ s,
    const float* __restrict__ up,
    const float* __restrict__ sp,
    const int*   __restrict__ idx,
    float* __restrict__ out,
    int grid)
{
    const int tid   = threadIdx.x;
    const int warp  = tid >> 5;
    const int lane  = tid & 31;
    const int r     = lane & 3;          /* 16B slice within a 64B row */
    const int nb    = lane >> 2;         /* neighbor sub-slot (0..7) per batch */

    __shared__ float ws[THREADS / 32];
    __shared__ int   s_islast;

    /* ================= Phase A: pack (4 threads per cell) ================= */
    {
        const int gt     = blockIdx.x * THREADS + tid;
        const int stride = grid * THREADS;            /* divisible by 32 */
        for (int unit = gt; unit < N_CELLS * 4; unit += stride) {
            const int cell = unit >> 2;
            const int rr   = unit & 3;                /* == lane&3 (stride%4==0) */
            const size_t sb = (size_t)cell * N_ISO;

            float x[8], v[8];
            #pragma unroll
            for (int k = 0; k < 8; k++) {
                const int m = 8 * rr + k;
                float xv = 0.f, pv = 0.f;
                if (m == 0)       { xv = u[cell];     pv = up[cell]; }
                else if (m <= 16) { xv = s[sb + m-1]; pv = sp[sb + m-1]; }
                x[k] = xv;
                v[k] = pv - xv;
            }

            float pvsq = 0.f;
            #pragma unroll
            for (int k = 0; k < 8; k++) pvsq += v[k]*v[k];
            pvsq += __shfl_xor_sync(0xffffffffu, pvsq, 1);
            pvsq += __shfl_xor_sync(0xffffffffu, pvsq, 2);
            const float inv = (pvsq > 0.f) ? rsqrtf(pvsq) : 0.f;  /* |v|=0 -> cos=0 (matches ref) */

            float vn[8];
            #pragma unroll
            for (int k = 0; k < 8; k++) vn[k] = v[k] * inv;

            g_hx[(size_t)cell * 4 + rr] = pack8h(x);
            g_hv[(size_t)cell * 4 + rr] = pack8h(vn);
        }
    }

    /* ============ Device-wide barrier (all `grid` blocks resident) ============ */
    __threadfence();
    __syncthreads();
    if (tid == 0) {
        const unsigned ph = g_phase;
        const unsigned t  = atomicInc(&g_bar_count, (unsigned)(grid - 1)); /* wraps -> reset */
        if (t == (unsigned)(grid - 1)) {
            g_phase = ph ^ 1u;                       /* release */
        } else {
            while (g_phase == ph) __nanosleep(64);   /* sense-reversal spin */
        }
        __threadfence();
    }
    __syncthreads();

    /* ================= Phase B: compute ================= */
    const int gwarp       = blockIdx.x * (THREADS / 32) + warp;
    const int total_warps = grid * (THREADS / 32);
    float lsum = 0.0f;

    for (int cell = gwarp; cell < N_CELLS; cell += total_warps) {
        __half2 a[4], vh[4];
        as_h2(g_hx[(size_t)cell * 4 + r], a);
        as_h2(g_hv[(size_t)cell * 4 + r], vh);

        const int ib = cell * KP1 + 1;

        /* Front-issue all four gathers (one LDG.128 covers 8 complete 64B rows). */
        const int j0 = idx[ib + (0  + nb)];
        const int j1 = idx[ib + (8  + nb)];
        const int j2 = idx[ib + (16 + nb)];
        const int j3 = idx[ib + ((24 + nb < KP1 - 1) ? 24 + nb : KP1 - 2)];
        const float4 w0 = g_hx[(size_t)j0 * 4 + r];
        const float4 w1 = g_hx[(size_t)j1 * 4 + r];
        const float4 w2 = g_hx[(size_t)j2 * 4 + r];
        const float4 w3 = g_hx[(size_t)j3 * 4 + r];

        float cmax = -3.0e38f;

        #pragma unroll
        for (int bt = 0; bt < 4; bt++) {
            const float4 w = (bt == 0) ? w0 : (bt == 1) ? w1 : (bt == 2) ? w2 : w3;
            const int slot = bt * 8 + nb;

            __half2 n[4];
            as_h2(w, n);

            const __half2 d0 = __hsub2(n[0], a[0]);
            const __half2 d1 = __hsub2(n[1], a[1]);
            const __half2 d2 = __hsub2(n[2], a[2]);
            const __half2 d3 = __hsub2(n[3], a[3]);

            __half2 ad = __hmul2(vh[0], d0);
            ad = __hfma2(vh[1], d1, ad);
            ad = __hfma2(vh[2], d2, ad);
            ad = __hfma2(vh[3], d3, ad);

            __half2 an = __hmul2(d0, d0);
            an = __hfma2(d1, d1, an);
            an = __hfma2(d2, d2, an);
            an = __hfma2(d3, d3, an);

            const float2 fd = __half22float2(ad);
            const float2 fn = __half22float2(an);
            float pd = fd.x + fd.y;
            float pn = fn.x + fn.y;

            pd += __shfl_xor_sync(0xffffffffu, pd, 1);
            pd += __shfl_xor_sync(0xffffffffu, pd, 2);
            pn += __shfl_xor_sync(0xffffffffu, pn, 1);
            pn += __shfl_xor_sync(0xffffffffu, pn, 2);

            if (r == 0 && slot < KP1 - 1) {
                const float c = (pn > 0.f) ? pd * rsqrtf(pn) : 0.f;
                cmax = fmaxf(cmax, c);
            }
        }

        /* Leaders at lanes 0,4,...,28 -> xor4/8/16 completes the warp max. */
        cmax = fmaxf(cmax, __shfl_xor_sync(0xffffffffu, cmax, 4));
        cmax = fmaxf(cmax, __shfl_xor_sync(0xffffffffu, cmax, 8));
        cmax = fmaxf(cmax, __shfl_xor_sync(0xffffffffu, cmax, 16));

        if (lane == 0) lsum += 1.0f - cmax;
    }

    if (lane == 0) ws[warp] = lsum;
    __syncthreads();

    if (tid == 0) {
        float bsum = 0.0f;
        #pragma unroll
        for (int w = 0; w < THREADS / 32; w++) bsum += ws[w];
        g_partials[blockIdx.x] = bsum;
        __threadfence();
        const unsigned t = atomicInc(&g_ticket, (unsigned)(grid - 1));  /* wraps -> replay safe */
        s_islast = (t == (unsigned)(grid - 1));
    }
    __syncthreads();

    if (s_islast) {
        float psum = 0.0f;
        const volatile float* vp = g_partials;
        for (int i = tid; i < grid; i += THREADS) psum += vp[i];
        #pragma unroll
        for (int o = 16; o > 0; o >>= 1)
            psum += __shfl_xor_sync(0xffffffffu, psum, o);
        if (lane == 0) ws[warp] = psum;
        __syncthreads();
        if (tid == 0) {
            float total = 0.0f;
            #pragma unroll
            for (int w = 0; w < THREADS / 32; w++) total += ws[w];
            out[0] = total * (1.0f / (float)N_CELLS);
        }
    }
}

extern "C" void kernel_launch(void* const* d_in, const int* in_sizes, int n_in,
                              void* d_out, int out_size) {
    const float* u   = (const float*)d_in[0];
    const float* s   = (const float*)d_in[1];
    const float* up  = (const float*)d_in[2];
    const float* sp  = (const float*)d_in[3];
    const int*   idx = (const int*)d_in[4];
    float* out = (float*)d_out;

    /* Deadlock-proof grid: exactly the number of co-resident blocks. */
    int dev = 0, sms = 148, maxb = BLOCKS_PER_SM;
    cudaGetDevice(&dev);
    cudaDeviceGetAttribute(&sms, cudaDevAttrMultiProcessorCount, dev);
    cudaOccupancyMaxActiveBlocksPerMultiprocessor(&maxb, fused_kernel, THREADS, 0);
    int grid = sms * maxb;
    if (grid > MAXGRID) grid = MAXGRID;
    if (grid < 1) grid = 1;

    fused_kernel<<<grid, THREADS>>>(u, s, up, sp, idx, out, grid);
}

// round 14
// speedup vs baseline: 1.0220x; 1.0220x over previous
#include <cuda_runtime.h>
#include <cuda_fp16.h>

#define N_CELLS 100000
#define N_ISO   16
#define KP1     31
#define THREADS 256
#define BLOCKS_PER_SM 6
#define MAXGRID 2048

/* fp16 packed rows, 64B each (4 x float4):
   x-row halves: [u, s0..s15, |x|^2 @17, 1.0 @18, vhat.x @19, 0...]
   v-row halves: [vhat_0..vhat_16, 0...]                                */
__device__ float4            g_hx[(size_t)N_CELLS * 4];
__device__ float4            g_hv[(size_t)N_CELLS * 4];
__device__ float             g_partials[MAXGRID];
__device__ unsigned int      g_ticket = 0;
__device__ unsigned int      g_bar_count = 0;
__device__ volatile unsigned g_phase = 0;

__device__ __forceinline__ float4 pack8h(const float* f)
{
    __half2 h0 = __floats2half2_rn(f[0], f[1]);
    __half2 h1 = __floats2half2_rn(f[2], f[3]);
    __half2 h2 = __floats2half2_rn(f[4], f[5]);
    __half2 h3 = __floats2half2_rn(f[6], f[7]);
    float4 o;
    o.x = __uint_as_float(*reinterpret_cast<unsigned*>(&h0));
    o.y = __uint_as_float(*reinterpret_cast<unsigned*>(&h1));
    o.z = __uint_as_float(*reinterpret_cast<unsigned*>(&h2));
    o.w = __uint_as_float(*reinterpret_cast<unsigned*>(&h3));
    return o;
}

__device__ __forceinline__ void as_h2(const float4 w, __half2* h)
{
    unsigned a0 = __float_as_uint(w.x), a1 = __float_as_uint(w.y);
    unsigned a2 = __float_as_uint(w.z), a3 = __float_as_uint(w.w);
    h[0] = *reinterpret_cast<__half2*>(&a0);
    h[1] = *reinterpret_cast<__half2*>(&a1);
    h[2] = *reinterpret_cast<__half2*>(&a2);
    h[3] = *reinterpret_cast<__half2*>(&a3);
}

__device__ __forceinline__ __half2 shfl_h2(__half2 v, int m)
{
    unsigned b = *reinterpret_cast<unsigned*>(&v);
    b = __shfl_xor_sync(0xffffffffu, b, m);
    return *reinterpret_cast<__half2*>(&b);
}

__global__ __launch_bounds__(THREADS, BLOCKS_PER_SM) void fused_kernel(
    const float* __restrict__ u,
    const float* __restrict__ s,
    const float* __restrict__ up,
    const float* __restrict__ sp,
    const int*   __restrict__ idx,
    float* __restrict__ out,
    int grid)
{
    const int tid   = threadIdx.x;
    const int warp  = tid >> 5;
    const int lane  = tid & 31;
    const int r     = lane & 3;          /* 16B slice within a 64B row */
    const int nb    = lane >> 2;         /* neighbor sub-slot (0..7) per batch */

    __shared__ float ws[THREADS / 32];
    __shared__ int   s_islast;

    /* ================= Phase A: pack (4 threads per cell) ================= */
    {
        const int gt     = blockIdx.x * THREADS + tid;
        const int stride = grid * THREADS;
        for (int unit = gt; unit < N_CELLS * 4; unit += stride) {
            const int cell = unit >> 2;
            const int rr   = unit & 3;                /* == lane&3 (stride%4==0) */
            const size_t sb = (size_t)cell * N_ISO;

            float x[8], v[8];
            #pragma unroll
            for (int k = 0; k < 8; k++) {
                const int m = 8 * rr + k;
                float xv = 0.f, pv = 0.f;
                if (m == 0)       { xv = u[cell];     pv = up[cell]; }
                else if (m <= 16) { xv = s[sb + m-1]; pv = sp[sb + m-1]; }
                x[k] = xv;
                v[k] = pv - xv;
            }

            float sv = 0.f, sxx = 0.f, sxv = 0.f;
            #pragma unroll
            for (int k = 0; k < 8; k++) { sv += v[k]*v[k]; sxx += x[k]*x[k]; sxv += x[k]*v[k]; }
            sv  += __shfl_xor_sync(0xffffffffu, sv,  1);
            sv  += __shfl_xor_sync(0xffffffffu, sv,  2);
            sxx += __shfl_xor_sync(0xffffffffu, sxx, 1);
            sxx += __shfl_xor_sync(0xffffffffu, sxx, 2);
            sxv += __shfl_xor_sync(0xffffffffu, sxv, 1);
            sxv += __shfl_xor_sync(0xffffffffu, sxv, 2);
            const float inv = (sv > 0.f) ? rsqrtf(sv) : 0.f;  /* |v|=0 -> vhat=0 -> cos=0 (matches ref) */

            float vn[8];
            #pragma unroll
            for (int k = 0; k < 8; k++) vn[k] = v[k] * inv;

            if (rr == 2) {            /* padding slots of slice 2: comps 17,18,19 */
                x[1] = sxx;           /* |x|^2   */
                x[2] = 1.0f;          /* constant */
                x[3] = sxv * inv;     /* vhat . x */
            }

            g_hx[(size_t)cell * 4 + rr] = pack8h(x);
            g_hv[(size_t)cell * 4 + rr] = pack8h(vn);
        }
    }

    /* ============ Device-wide barrier (all `grid` blocks resident) ============ */
    __threadfence();
    __syncthreads();
    if (tid == 0) {
        const unsigned ph = g_phase;
        const unsigned t  = atomicInc(&g_bar_count, (unsigned)(grid - 1)); /* wraps -> reset */
        if (t == (unsigned)(grid - 1)) {
            g_phase = ph ^ 1u;
        } else {
            while (g_phase == ph) __nanosleep(64);
        }
        __threadfence();
    }
    __syncthreads();

    /* ================= Phase B: compute ================= */
    const int gwarp       = blockIdx.x * (THREADS / 32) + warp;
    const int total_warps = grid * (THREADS / 32);
    float lsum = 0.0f;

    for (int cell = gwarp; cell < N_CELLS; cell += total_warps) {
        __half2 aq[4], vq[4];
        as_h2(g_hx[(size_t)cell * 4 + r], aq);
        as_h2(g_hv[(size_t)cell * 4 + r], vq);

        /* Build query vectors so that  aq.n = -pn/2  and  vq.n = pd  exactly.
           Only slice r==2 holds the padding components (17,18,19). */
        if (r == 2) {
            const __half na2 = __high2half(aq[0]);            /* |a|^2        */
            const __half vhx = __high2half(aq[1]);            /* vhat . a     */
            /* aq: comp17 -> -0.5 ; comp18 -> -0.5*|a|^2 ; comp19 -> 0 */
            unsigned b0 = *reinterpret_cast<unsigned*>(&aq[0]);
            b0 = (b0 & 0x0000FFFFu) | 0xB8000000u;            /* high := -0.5 fp16 */
            aq[0] = *reinterpret_cast<__half2*>(&b0);
            aq[1] = __halves2half2(__hmul(na2, __float2half(-0.5f)), __float2half(0.f));
            /* vq: comp18 -> -(vhat.a) ; comp19 -> 0 (rest already 0) */
            vq[1] = __halves2half2(__hneg(vhx), __float2half(0.f));
        }

        const int ib = cell * KP1 + 1;

        /* Front-issue all four gathers (one LDG.128 covers 8 complete 64B rows). */
        const int j0 = idx[ib + (0  + nb)];
        const int j1 = idx[ib + (8  + nb)];
        const int j2 = idx[ib + (16 + nb)];
        const int j3 = idx[ib + ((24 + nb < KP1 - 1) ? 24 + nb : KP1 - 2)];
        const float4 w0 = g_hx[(size_t)j0 * 4 + r];
        const float4 w1 = g_hx[(size_t)j1 * 4 + r];
        const float4 w2 = g_hx[(size_t)j2 * 4 + r];
        const float4 w3 = g_hx[(size_t)j3 * 4 + r];

        float cmax = -3.0e38f;

        #pragma unroll
        for (int bt = 0; bt < 4; bt++) {
            const float4 w = (bt == 0) ? w0 : (bt == 1) ? w1 : (bt == 2) ? w2 : w3;
            const int slot = bt * 8 + nb;

            __half2 n[4];
            as_h2(w, n);

            /* Two dot products of the RAW row with the query vectors. */
            __half2 A = __hmul2(aq[0], n[0]);
            A = __hfma2(aq[1], n[1], A);
            A = __hfma2(aq[2], n[2], A);
            A = __hfma2(aq[3], n[3], A);

            __half2 V = __hmul2(vq[0], n[0]);
            V = __hfma2(vq[1], n[1], V);
            V = __hfma2(vq[2], n[2], V);
            V = __hfma2(vq[3], n[3], V);

            /* C = { pa_partial, pv_partial } in one half2. */
            __half2 C = __hadd2(__lows2half2(A, V), __highs2half2(A, V));

            /* Quad reduce: 2 shfl + 2 hadd2 (covers both scalars at once). */
            C = __hadd2(C, shfl_h2(C, 1));
            C = __hadd2(C, shfl_h2(C, 2));

            if (r == 0 && slot < KP1 - 1) {
                const float2 f = __half22float2(C);
                const float pn = -2.0f * f.x;          /* |n-a|^2 */
                const float pd = f.y;                  /* vhat.(n-a) */
                const float c  = (pn > 0.f) ? pd * rsqrtf(pn) : 0.f;
                cmax = fmaxf(cmax, c);
            }
        }

        /* Leaders at lanes 0,4,...,28 -> xor4/8/16 completes the warp max. */
        cmax = fmaxf(cmax, __shfl_xor_sync(0xffffffffu, cmax, 4));
        cmax = fmaxf(cmax, __shfl_xor_sync(0xffffffffu, cmax, 8));
        cmax = fmaxf(cmax, __shfl_xor_sync(0xffffffffu, cmax, 16));

        if (lane == 0) lsum += 1.0f - cmax;
    }

    if (lane == 0) ws[warp] = lsum;
    __syncthreads();

    if (tid == 0) {
        float bsum = 0.0f;
        #pragma unroll
        for (int w = 0; w < THREADS / 32; w++) bsum += ws[w];
        g_partials[blockIdx.x] = bsum;
        __threadfence();
        const unsigned t = atomicInc(&g_ticket, (unsigned)(grid - 1));  /* wraps -> replay safe */
        s_islast = (t == (unsigned)(grid - 1));
    }
    __syncthreads();

    if (s_islast) {
        float psum = 0.0f;
        const volatile float* vp = g_partials;
        for (int i = tid; i < grid; i += THREADS) psum += vp[i];
        #pragma unroll
        for (int o = 16; o > 0; o >>= 1)
            psum += __shfl_xor_sync(0xffffffffu, psum, o);
        if (lane == 0) ws[warp] = psum;
        __syncthreads();
        if (tid == 0) {
            float total = 0.0f;
            #pragma unroll
            for (int w = 0; w < THREADS / 32; w++) total += ws[w];
            out[0] = total * (1.0f / (float)N_CELLS);
        }
    }
}

extern "C" void kernel_launch(void* const* d_in, const int* in_sizes, int n_in,
                              void* d_out, int out_size) {
    const float* u   = (const float*)d_in[0];
    const float* s   = (const float*)d_in[1];
    const float* up  = (const float*)d_in[2];
    const float* sp  = (const float*)d_in[3];
    const int*   idx = (const int*)d_in[4];
    float* out = (float*)d_out;

    /* Deadlock-proof grid: exactly the number of co-resident blocks. */
    int dev = 0, sms = 148, maxb = BLOCKS_PER_SM;
    cudaGetDevice(&dev);
    cudaDeviceGetAttribute(&sms, cudaDevAttrMultiProcessorCount, dev);
    cudaOccupancyMaxActiveBlocksPerMultiprocessor(&maxb, fused_kernel, THREADS, 0);
    int grid = sms * maxb;
    if (grid > MAXGRID) grid = MAXGRID;
    if (grid < 1) grid = 1;

    fused_kernel<<<grid, THREADS>>>(u, s, up, sp, idx, out, grid);
}

// round 15
// speedup vs baseline: 1.0236x; 1.0015x over previous
#include <cuda_runtime.h>
#include <cuda_fp16.h>

#define N_CELLS 100000
#define N_ISO   16
#define KP1     31
#define THREADS 256
#define BLOCKS_PER_SM 6
#define MAXGRID 2048

/* fp16 packed rows, 64B each (4 x float4):
   x-row halves: [u, s0..s15, |x|^2 @17, 1.0 @18, vhat.x @19, 0...]
   v-row halves: [vhat_0..vhat_16, 0...]                                */
__device__ float4            g_hx[(size_t)N_CELLS * 4];
__device__ float4            g_hv[(size_t)N_CELLS * 4];
__device__ float             g_partials[MAXGRID];
__device__ unsigned int      g_ticket = 0;
__device__ unsigned int      g_bar_count = 0;
__device__ volatile unsigned g_phase = 0;

__device__ __forceinline__ float4 pack8h(const float* f)
{
    __half2 h0 = __floats2half2_rn(f[0], f[1]);
    __half2 h1 = __floats2half2_rn(f[2], f[3]);
    __half2 h2 = __floats2half2_rn(f[4], f[5]);
    __half2 h3 = __floats2half2_rn(f[6], f[7]);
    float4 o;
    o.x = __uint_as_float(*reinterpret_cast<unsigned*>(&h0));
    o.y = __uint_as_float(*reinterpret_cast<unsigned*>(&h1));
    o.z = __uint_as_float(*reinterpret_cast<unsigned*>(&h2));
    o.w = __uint_as_float(*reinterpret_cast<unsigned*>(&h3));
    return o;
}

__device__ __forceinline__ void as_h2(const float4 w, __half2* h)
{
    unsigned a0 = __float_as_uint(w.x), a1 = __float_as_uint(w.y);
    unsigned a2 = __float_as_uint(w.z), a3 = __float_as_uint(w.w);
    h[0] = *reinterpret_cast<__half2*>(&a0);
    h[1] = *reinterpret_cast<__half2*>(&a1);
    h[2] = *reinterpret_cast<__half2*>(&a2);
    h[3] = *reinterpret_cast<__half2*>(&a3);
}

__device__ __forceinline__ __half2 shfl_h2(__half2 v, int m)
{
    unsigned b = *reinterpret_cast<unsigned*>(&v);
    b = __shfl_xor_sync(0xffffffffu, b, m);
    return *reinterpret_cast<__half2*>(&b);
}

__global__ __launch_bounds__(THREADS, BLOCKS_PER_SM) void fused_kernel(
    const float* __restrict__ u,
    const float* __restrict__ s,
    const float* __restrict__ up,
    const float* __restrict__ sp,
    const int*   __restrict__ idx,
    float* __restrict__ out,
    int grid)
{
    const int tid   = threadIdx.x;
    const int warp  = tid >> 5;
    const int lane  = tid & 31;
    const int r     = lane & 3;          /* 16B slice within a 64B row */
    const int nb    = lane >> 2;         /* neighbor sub-slot (0..7) per batch */

    __shared__ float ws[THREADS / 32];
    __shared__ int   s_islast;

    /* ================= Phase A: pack (4 threads per cell) ================= */
    {
        const int gt     = blockIdx.x * THREADS + tid;
        const int stride = grid * THREADS;
        for (int unit = gt; unit < N_CELLS * 4; unit += stride) {
            const int cell = unit >> 2;
            const int rr   = unit & 3;                /* == lane&3 (stride%4==0) */
            const size_t sb = (size_t)cell * N_ISO;

            float x[8], v[8];
            #pragma unroll
            for (int k = 0; k < 8; k++) {
                const int m = 8 * rr + k;
                float xv = 0.f, pv = 0.f;
                if (m == 0)       { xv = u[cell];     pv = up[cell]; }
                else if (m <= 16) { xv = s[sb + m-1]; pv = sp[sb + m-1]; }
                x[k] = xv;
                v[k] = pv - xv;
            }

            float sv = 0.f, sxx = 0.f, sxv = 0.f;
            #pragma unroll
            for (int k = 0; k < 8; k++) { sv += v[k]*v[k]; sxx += x[k]*x[k]; sxv += x[k]*v[k]; }
            sv  += __shfl_xor_sync(0xffffffffu, sv,  1);
            sv  += __shfl_xor_sync(0xffffffffu, sv,  2);
            sxx += __shfl_xor_sync(0xffffffffu, sxx, 1);
            sxx += __shfl_xor_sync(0xffffffffu, sxx, 2);
            sxv += __shfl_xor_sync(0xffffffffu, sxv, 1);
            sxv += __shfl_xor_sync(0xffffffffu, sxv, 2);
            const float inv = (sv > 0.f) ? rsqrtf(sv) : 0.f;  /* |v|=0 -> vhat=0 -> cos=0 (matches ref) */

            float vn[8];
            #pragma unroll
            for (int k = 0; k < 8; k++) vn[k] = v[k] * inv;

            if (rr == 2) {            /* padding slots of slice 2: comps 17,18,19 */
                x[1] = sxx;           /* |x|^2   */
                x[2] = 1.0f;          /* constant */
                x[3] = sxv * inv;     /* vhat . x */
            }

            g_hx[(size_t)cell * 4 + rr] = pack8h(x);
            g_hv[(size_t)cell * 4 + rr] = pack8h(vn);
        }
    }

    /* ============ Device-wide barrier (all `grid` blocks resident) ============ */
    __threadfence();
    __syncthreads();
    if (tid == 0) {
        const unsigned ph = g_phase;
        const unsigned t  = atomicInc(&g_bar_count, (unsigned)(grid - 1)); /* wraps -> reset */
        if (t == (unsigned)(grid - 1)) {
            g_phase = ph ^ 1u;
        } else {
            while (g_phase == ph) __nanosleep(64);
        }
        __threadfence();
    }
    __syncthreads();

    /* ================= Phase B: compute ================= */
    const int gwarp       = blockIdx.x * (THREADS / 32) + warp;
    const int total_warps = grid * (THREADS / 32);
    float lsum = 0.0f;

    for (int cell = gwarp; cell < N_CELLS; cell += total_warps) {
        __half2 aq[4], vq[4];
        as_h2(g_hx[(size_t)cell * 4 + r], aq);
        as_h2(g_hv[(size_t)cell * 4 + r], vq);

        /* Build query vectors so that  aq.n = -pn/2  and  vq.n = pd  exactly.
           Only slice r==2 holds the padding components (17,18,19). */
        if (r == 2) {
            const __half na2 = __high2half(aq[0]);            /* |a|^2        */
            const __half vhx = __high2half(aq[1]);            /* vhat . a     */
            /* aq: comp17 -> -0.5 ; comp18 -> -0.5*|a|^2 ; comp19 -> 0 */
            unsigned b0 = *reinterpret_cast<unsigned*>(&aq[0]);
            b0 = (b0 & 0x0000FFFFu) | 0xB8000000u;            /* high := -0.5 fp16 */
            aq[0] = *reinterpret_cast<__half2*>(&b0);
            aq[1] = __halves2half2(__hmul(na2, __float2half(-0.5f)), __float2half(0.f));
            /* vq: comp18 -> -(vhat.a) ; comp19 -> 0 (rest already 0) */
            vq[1] = __halves2half2(__hneg(vhx), __float2half(0.f));
        }

        const int ib = cell * KP1 + 1;

        /* Front-issue all four gathers (one LDG.128 covers 8 complete 64B rows). */
        const int j0 = idx[ib + (0  + nb)];
        const int j1 = idx[ib + (8  + nb)];
        const int j2 = idx[ib + (16 + nb)];
        const int j3 = idx[ib + ((24 + nb < KP1 - 1) ? 24 + nb : KP1 - 2)];
        const float4 w0 = g_hx[(size_t)j0 * 4 + r];
        const float4 w1 = g_hx[(size_t)j1 * 4 + r];
        const float4 w2 = g_hx[(size_t)j2 * 4 + r];
        const float4 w3 = g_hx[(size_t)j3 * 4 + r];

        float cmax = -3.0e38f;

        #pragma unroll
        for (int bt = 0; bt < 4; bt++) {
            const float4 w = (bt == 0) ? w0 : (bt == 1) ? w1 : (bt == 2) ? w2 : w3;
            const int slot = bt * 8 + nb;

            __half2 n[4];
            as_h2(w, n);

            /* Two dot products of the RAW row with the query vectors. */
            __half2 A = __hmul2(aq[0], n[0]);
            A = __hfma2(aq[1], n[1], A);
            A = __hfma2(aq[2], n[2], A);
            A = __hfma2(aq[3], n[3], A);

            __half2 V = __hmul2(vq[0], n[0]);
            V = __hfma2(vq[1], n[1], V);
            V = __hfma2(vq[2], n[2], V);
            V = __hfma2(vq[3], n[3], V);

            /* C = { pa_partial, pv_partial } in one half2. */
            __half2 C = __hadd2(__lows2half2(A, V), __highs2half2(A, V));

            /* Quad reduce: 2 shfl + 2 hadd2 (covers both scalars at once). */
            C = __hadd2(C, shfl_h2(C, 1));
            C = __hadd2(C, shfl_h2(C, 2));

            if (r == 0 && slot < KP1 - 1) {
                const float2 f = __half22float2(C);
                const float pn = -2.0f * f.x;          /* |n-a|^2 */
                const float pd = f.y;                  /* vhat.(n-a) */
                const float c  = (pn > 0.f) ? pd * rsqrtf(pn) : 0.f;
                cmax = fmaxf(cmax, c);
            }
        }

        /* Leaders at lanes 0,4,...,28 -> xor4/8/16 completes the warp max. */
        cmax = fmaxf(cmax, __shfl_xor_sync(0xffffffffu, cmax, 4));
        cmax = fmaxf(cmax, __shfl_xor_sync(0xffffffffu, cmax, 8));
        cmax = fmaxf(cmax, __shfl_xor_sync(0xffffffffu, cmax, 16));

        if (lane == 0) lsum += 1.0f - cmax;
    }

    if (lane == 0) ws[warp] = lsum;
    __syncthreads();

    if (tid == 0) {
        float bsum = 0.0f;
        #pragma unroll
        for (int w = 0; w < THREADS / 32; w++) bsum += ws[w];
        g_partials[blockIdx.x] = bsum;
        __threadfence();
        const unsigned t = atomicInc(&g_ticket, (unsigned)(grid - 1));  /* wraps -> replay safe */
        s_islast = (t == (unsigned)(grid - 1));
    }
    __syncthreads();

    if (s_islast) {
        float psum = 0.0f;
        const volatile float* vp = g_partials;
        for (int i = tid; i < grid; i += THREADS) psum += vp[i];
        #pragma unroll
        for (int o = 16; o > 0; o >>= 1)
            psum += __shfl_xor_sync(0xffffffffu, psum, o);
        if (lane == 0) ws[warp] = psum;
        __syncthreads();
        if (tid == 0) {
            float total = 0.0f;
            #pragma unroll
            for (int w = 0; w < THREADS / 32; w++) total += ws[w];
            out[0] = total * (1.0f / (float)N_CELLS);
        }
    }
}

extern "C" void kernel_launch(void* const* d_in, const int* in_sizes, int n_in,
                              void* d_out, int out_size) {
    const float* u   = (const float*)d_in[0];
    const float* s   = (const float*)d_in[1];
    const float* up  = (const float*)d_in[2];
    const float* sp  = (const float*)d_in[3];
    const int*   idx = (const int*)d_in[4];
    float* out = (float*)d_out;

    /* Deadlock-proof grid: exactly the number of co-resident blocks. */
    int dev = 0, sms = 148, maxb = BLOCKS_PER_SM;
    cudaGetDevice(&dev);
    cudaDeviceGetAttribute(&sms, cudaDevAttrMultiProcessorCount, dev);
    cudaOccupancyMaxActiveBlocksPerMultiprocessor(&maxb, fused_kernel, THREADS, 0);
    int grid = sms * maxb;
    if (grid > MAXGRID) grid = MAXGRID;
    if (grid < 1) grid = 1;

    fused_kernel<<<grid, THREADS>>>(u, s, up, sp, idx, out, grid);
}